// round 10
// baseline (speedup 1.0000x reference)
#include <cuda_runtime.h>
#include <math.h>

#define NQ    6
#define BATCH 256
#define HID   256
#define INP   784
#define KS    4
#define LAM1  0.9986666666666667f
#define LAM2  0.9866666666666667f
#define LAM12 (LAM1*LAM2)
#define PI_F  3.14159265358979323846f
#define NPTM  6
#define GRID  134          // 6 PTM + 128 GEMM blocks, all co-resident (<=148 SMs)

typedef unsigned long long u64;

__device__ float g_hp[KS * BATCH * HID];   // K-split partial GEMM outputs
__device__ float g_Tct[768 * 8];           // evolved observables, [term][obs] zero-padded
__device__ unsigned g_bar;                 // monotonic ticket barrier (never reset)

// ---------- compile-time tables ----------
struct alignas(16) Tabs {
    short ring[3][4096];   // signed permutation: tg | neg<<12
    short s4of[736];       // base-3 index -> base-4 Pauli index (1->X, 2->Z), padded
};

static constexpr unsigned char LUTc[16] = {0,4,11,15, 5,1,14,26, 6,2,29,9, 3,7,8,12};

static constexpr Tabs make_tabs() {
    Tabs T = {};
    for (int r = 1; r <= 3; r++) {
        for (int s = 0; s < 4096; s++) {
            int cur = s, neg = 0;
            for (int i = 5; i >= 0; --i) {
                int c = i, t = (i + r) % 6;
                int a = (cur >> (2*c)) & 3, b = (cur >> (2*t)) & 3;
                int lv = LUTc[a*4 + b];
                cur = (cur & ~((3 << (2*c)) | (3 << (2*t))))
                    | ((lv & 3) << (2*c)) | (((lv >> 2) & 3) << (2*t));
                neg ^= lv >> 4;
            }
            T.ring[r-1][s] = (short)(cur | (neg << 12));
        }
    }
    for (int s = 0; s < 729; s++) {
        int tmp = s, s4 = 0;
        for (int q = 0; q < 6; q++) {
            int dd = tmp % 3; tmp /= 3;
            if (dd == 1) s4 |= 1 << (2*q);
            else if (dd == 2) s4 |= 3 << (2*q);
        }
        T.s4of[s] = (short)s4;
    }
    return T;
}
__device__ constexpr Tabs g_tabs = make_tabs();

#define SMEM_BYTES 43008

__device__ __forceinline__ int PHYS(int s) {
    return s ^ (((s >> 4) & 7) << 2) ^ (((s >> 8) & 1) << 4);
}

__device__ __forceinline__ void ffma2(u64& d, u64 a, u64 b) {
    asm("fma.rn.f32x2 %0, %1, %2, %0;" : "+l"(d) : "l"(a), "l"(b));
}

// ---------- PTM passes ----------
__device__ __forceinline__ void rotAB(float* m, const float* A0, const float* A1, int tid)
{
    float4* m4 = reinterpret_cast<float4*>(m);
    const int P = (tid & 7) ^ (((tid >> 4) & 1) << 2);
    float4 v[4];
#pragma unroll
    for (int j = 0; j < 4; j++) v[j] = m4[(4*tid + j) ^ P];
#pragma unroll
    for (int j = 0; j < 4; j++) {
        float x = v[j].y, y = v[j].z, z = v[j].w;
        v[j].y = A0[0]*x + A0[1]*y + A0[2]*z;
        v[j].z = A0[3]*x + A0[4]*y + A0[5]*z;
        v[j].w = A0[6]*x + A0[7]*y + A0[8]*z;
    }
    {
        float4 a = v[1], b = v[2], c = v[3];
        v[1].x = A1[0]*a.x + A1[1]*b.x + A1[2]*c.x;
        v[1].y = A1[0]*a.y + A1[1]*b.y + A1[2]*c.y;
        v[1].z = A1[0]*a.z + A1[1]*b.z + A1[2]*c.z;
        v[1].w = A1[0]*a.w + A1[1]*b.w + A1[2]*c.w;
        v[2].x = A1[3]*a.x + A1[4]*b.x + A1[5]*c.x;
        v[2].y = A1[3]*a.y + A1[4]*b.y + A1[5]*c.y;
        v[2].z = A1[3]*a.z + A1[4]*b.z + A1[5]*c.z;
        v[2].w = A1[3]*a.w + A1[4]*b.w + A1[5]*c.w;
        v[3].x = A1[6]*a.x + A1[7]*b.x + A1[8]*c.x;
        v[3].y = A1[6]*a.y + A1[7]*b.y + A1[8]*c.y;
        v[3].z = A1[6]*a.z + A1[7]*b.z + A1[8]*c.z;
        v[3].w = A1[6]*a.w + A1[7]*b.w + A1[8]*c.w;
    }
#pragma unroll
    for (int j = 0; j < 4; j++) m4[(4*tid + j) ^ P] = v[j];
    __syncthreads();
}

__device__ __forceinline__ void rot2dig(float v[16], const float* Alo, const float* Ahi)
{
#pragma unroll
    for (int g = 0; g < 4; g++) {
        float x = v[g*4+1], y = v[g*4+2], z = v[g*4+3];
        v[g*4+1] = Alo[0]*x + Alo[1]*y + Alo[2]*z;
        v[g*4+2] = Alo[3]*x + Alo[4]*y + Alo[5]*z;
        v[g*4+3] = Alo[6]*x + Alo[7]*y + Alo[8]*z;
    }
#pragma unroll
    for (int c = 0; c < 4; c++) {
        float x = v[c+4], y = v[c+8], z = v[c+12];
        v[c+4]  = Ahi[0]*x + Ahi[1]*y + Ahi[2]*z;
        v[c+8]  = Ahi[3]*x + Ahi[4]*y + Ahi[5]*z;
        v[c+12] = Ahi[6]*x + Ahi[7]*y + Ahi[8]*z;
    }
}

__device__ __forceinline__ void rotCD(float* m, const float* A2, const float* A3, int tid)
{
    const int lo = tid & 15, hi = (tid >> 4) << 8;
    float v[16];
#pragma unroll
    for (int e = 0; e < 16; e++) v[e] = m[PHYS(hi | (e << 4) | lo)];
    rot2dig(v, A2, A3);
#pragma unroll
    for (int e = 0; e < 16; e++) m[PHYS(hi | (e << 4) | lo)] = v[e];
    __syncthreads();
}

__device__ __forceinline__ void rotEF(float* m, const float* A4, const float* A5, int tid,
                                      const short* ring, bool dep)
{
    float v[16];
#pragma unroll
    for (int e = 0; e < 16; e++) v[e] = m[PHYS((e << 8) | tid)];
    rot2dig(v, A4, A5);
    if (ring) {
        __syncthreads();
#pragma unroll
        for (int e = 0; e < 16; e++) {
            int s = (e << 8) | tid;
            float val = v[e];
            if (dep) {
                float sc = 1.f;
#pragma unroll
                for (int q = 0; q < 6; q++)
                    if ((s >> (2*q)) & 3) sc *= (q < 5) ? LAM12 : LAM1;
                val *= sc;
            }
            int tg = ring[s];
            m[PHYS(tg & 4095)] = (tg & 4096) ? -val : val;
        }
    } else {
#pragma unroll
        for (int e = 0; e < 16; e++) m[PHYS((e << 8) | tid)] = v[e];
    }
    __syncthreads();
}

// phase-2 smem overlay
struct K2S {
    float4 red[8];
    float hnA[HID], hnB[HID];
    float tqA[18], tqB[18];
    float ploA[27], phiA[27], ploB[27], phiB[27];
    float r6A[8][6], r6B[8][6];
    float evA[NQ], evB[NQ];
};

// ---------- fused kernel ----------
__global__ void __launch_bounds__(256) kall(const float* __restrict__ x, const float* __restrict__ W1,
                                            const float* __restrict__ sw, const float* __restrict__ tw,
                                            const float* __restrict__ b1v,
                                            const float* __restrict__ lng, const float* __restrict__ lnb,
                                            const float* __restrict__ W2, const float* __restrict__ b2,
                                            const float* __restrict__ Wp, const float* __restrict__ bp,
                                            float* __restrict__ out)
{
    __shared__ __align__(16) char su[SMEM_BYTES];
    const int tid = threadIdx.x;
    const int blk = blockIdx.x;
    const int lane = tid & 31, w = tid >> 5;

    // ================= phase 1 =================
    if (blk < NPTM) {
        float* m = reinterpret_cast<float*>(su);
        short* rtab = reinterpret_cast<short*>(su + 16384);
        float (*mats)[10] = reinterpret_cast<float(*)[10]>(su + 40960);

        {
            const uint4* srcT = reinterpret_cast<const uint4*>(&g_tabs.ring[0][0]);
            uint4* dstT = reinterpret_cast<uint4*>(rtab);
#pragma unroll
            for (int i = 0; i < 6; i++) dstT[tid + i*256] = srcT[tid + i*256];
        }
        if (tid < 30) {
            const float* wsrc = (tid < 18) ? (sw + tid*3) : (tw + (tid - 18)*3);
            float sp, cp, st, ct, sw_, cw_;
            sincosf(wsrc[0], &sp, &cp);
            sincosf(wsrc[1], &st, &ct);
            sincosf(wsrc[2], &sw_, &cw_);
            mats[tid][0] =  cp*ct*cw_ - sp*sw_;
            mats[tid][1] =  cp*ct*sw_ + sp*cw_;
            mats[tid][2] = -cp*st;
            mats[tid][3] = -sp*ct*cw_ - cp*sw_;
            mats[tid][4] = -sp*ct*sw_ + cp*cw_;
            mats[tid][5] =  sp*st;
            mats[tid][6] =  st*cw_;
            mats[tid][7] =  st*sw_;
            mats[tid][8] =  ct;
        }
        const int k = blk;
#pragma unroll
        for (int e = 0; e < 16; e++) m[PHYS((e << 8) | tid)] = 0.f;
        __syncthreads();
        if (tid == 0) {
            int tg = g_tabs.ring[1][3 << (2*k)];    // first ring (r=2) applied analytically
            m[PHYS(tg & 4095)] = (tg & 4096) ? -LAM1 : LAM1;
        }
        __syncthreads();

        rotAB(m, mats[24], mats[25], tid);
        rotCD(m, mats[26], mats[27], tid);
        rotEF(m, mats[28], mats[29], tid, rtab + 0*4096, false);   // + R1
        rotAB(m, mats[18], mats[19], tid);
        rotCD(m, mats[20], mats[21], tid);
        rotEF(m, mats[22], mats[23], tid, rtab + 2*4096, true);    // + dep + R3
        rotAB(m, mats[12], mats[13], tid);
        rotCD(m, mats[14], mats[15], tid);
        rotEF(m, mats[16], mats[17], tid, rtab + 1*4096, false);   // + R2
        rotAB(m, mats[6],  mats[7],  tid);
        rotCD(m, mats[8],  mats[9],  tid);
        rotEF(m, mats[10], mats[11], tid, rtab + 0*4096, false);   // + R1
        rotAB(m, mats[0],  mats[1],  tid);
        rotCD(m, mats[2],  mats[3],  tid);
        rotEF(m, mats[4],  mats[5],  tid, (const short*)0, false);

        for (int i = tid; i < 768; i += 256)
            g_Tct[i*8 + k] = (i < 729) ? m[PHYS((int)g_tabs.s4of[i])] : 0.f;
    } else {
        const int g    = blk - NPTM;
        const int rowT = g >> 4;
        const int colT = (g >> 2) & 3;
        const int kp   = g & 3;
        const int row0 = rowT * 32, col0 = colT * 64;

        float* ws = reinterpret_cast<float*>(su);            // [64][102]
        float* xs = reinterpret_cast<float*>(su + 26112);    // [32][100]
        const int r0 = w * 4;

        u64 acc2[4][2] = {{0ull,0ull},{0ull,0ull},{0ull,0ull},{0ull,0ull}};
        const float2* W1_2 = reinterpret_cast<const float2*>(W1);
        const float2* x_2  = reinterpret_cast<const float2*>(x);

#pragma unroll 1
        for (int ch = 0; ch < 2; ch++) {
            const int kof = kp*98 + ch*49;
            for (int idx = tid; idx < 64*49; idx += 256) {
                int c = idx / 49, j2 = idx - c*49;
                float2 wv = W1_2[(col0 + c)*392 + kof + j2];
                ws[c*102 + 2*j2]     = wv.x;
                ws[c*102 + 2*j2 + 1] = wv.y;
            }
            if (tid < 128) ws[(tid >> 1)*102 + 98 + (tid & 1)] = 0.f;
            for (int idx = tid; idx < 32*49; idx += 256) {
                int r = idx / 49, j2 = idx - r*49;
                float2 xv = x_2[(row0 + r)*392 + kof + j2];
                xs[r*100 + 2*j2]     = xv.x;
                xs[r*100 + 2*j2 + 1] = xv.y;
            }
            if (tid < 64) xs[(tid >> 1)*100 + 98 + (tid & 1)] = 0.f;
            __syncthreads();

            const u64* wl0 = reinterpret_cast<const u64*>(ws + lane*102);
            const u64* wl1 = reinterpret_cast<const u64*>(ws + (lane + 32)*102);
#pragma unroll 5
            for (int j = 0; j < 25; j++) {
                u64 w00 = wl0[2*j], w01 = wl0[2*j + 1];
                u64 w10 = wl1[2*j], w11 = wl1[2*j + 1];
#pragma unroll
                for (int r = 0; r < 4; r++) {
                    const u64* xr = reinterpret_cast<const u64*>(xs + (r0 + r)*100);
                    u64 x0 = xr[2*j], x1 = xr[2*j + 1];
                    ffma2(acc2[r][0], x0, w00);
                    ffma2(acc2[r][0], x1, w01);
                    ffma2(acc2[r][1], x0, w10);
                    ffma2(acc2[r][1], x1, w11);
                }
            }
            __syncthreads();
        }
#pragma unroll
        for (int i = 0; i < 4; i++) {
            int row = row0 + r0 + i;
            float2 a0 = *reinterpret_cast<float2*>(&acc2[i][0]);
            float2 a1 = *reinterpret_cast<float2*>(&acc2[i][1]);
            g_hp[kp*65536 + row*256 + col0 + lane]      = a0.x + a0.y;
            g_hp[kp*65536 + row*256 + col0 + 32 + lane] = a1.x + a1.y;
        }
    }

    // prefetch phase-2 parameters (independent of phase-1 results; hidden by barrier wait)
    float pb1 = 0.f, pg = 0.f, pbb = 0.f;
    float w2r[8];
    if (blk >= NPTM) {
        pb1 = b1v[tid]; pg = lng[tid]; pbb = lnb[tid];
        if (w < NQ) {
#pragma unroll
            for (int it = 0; it < 8; it++) w2r[it] = W2[w*256 + lane + it*32];
        }
    }

    // ================= device-wide barrier (monotonic ticket; reset-free) =================
    __threadfence();
    if (tid == 0) {
        unsigned ticket = atomicAdd(&g_bar, 1u);
        unsigned target = (ticket / GRID + 1u) * GRID;
        while (atomicAdd(&g_bar, 0u) < target) __nanosleep(64);
    }
    __syncthreads();
    if (blk < NPTM) return;

    // ================= phase 2: k2 for rows 2*(blk-6), 2*(blk-6)+1 =================
    K2S* S = reinterpret_cast<K2S*>(su);
    const int rA = (blk - NPTM) * 2, rB = rA + 1;

    const float4* Tct4 = reinterpret_cast<const float4*>(g_Tct);
    float4 tA[3], tB[3];
#pragma unroll
    for (int j = 0; j < 3; j++) {
        int ss = tid + j * 256;
        tA[j] = __ldcg(&Tct4[ss*2]);
        tB[j] = __ldcg(&Tct4[ss*2 + 1]);
    }

    float hA = __ldcg(&g_hp[rA*HID + tid]) + __ldcg(&g_hp[65536 + rA*HID + tid])
             + __ldcg(&g_hp[131072 + rA*HID + tid]) + __ldcg(&g_hp[196608 + rA*HID + tid]) + pb1;
    float hB = __ldcg(&g_hp[rB*HID + tid]) + __ldcg(&g_hp[65536 + rB*HID + tid])
             + __ldcg(&g_hp[131072 + rB*HID + tid]) + __ldcg(&g_hp[196608 + rB*HID + tid]) + pb1;
    hA = fmaxf(hA, 0.f);
    hB = fmaxf(hB, 0.f);

    float s0 = hA, q0 = hA*hA, s1 = hB, q1 = hB*hB;
#pragma unroll
    for (int o = 16; o > 0; o >>= 1) {
        s0 += __shfl_down_sync(~0u, s0, o);
        q0 += __shfl_down_sync(~0u, q0, o);
        s1 += __shfl_down_sync(~0u, s1, o);
        q1 += __shfl_down_sync(~0u, q1, o);
    }
    if (lane == 0) S->red[w] = make_float4(s0, q0, s1, q1);
    __syncthreads();
    if (tid < 8) {
        float4 t = S->red[tid];
#pragma unroll
        for (int o = 4; o > 0; o >>= 1) {
            t.x += __shfl_down_sync(0xffu, t.x, o);
            t.y += __shfl_down_sync(0xffu, t.y, o);
            t.z += __shfl_down_sync(0xffu, t.z, o);
            t.w += __shfl_down_sync(0xffu, t.w, o);
        }
        if (tid == 0) S->red[0] = t;
    }
    __syncthreads();
    float4 R = S->red[0];
    float muA = R.x * (1.f/256.f), vaA = R.y * (1.f/256.f) - muA*muA;
    float muB = R.z * (1.f/256.f), vaB = R.w * (1.f/256.f) - muB*muB;
    S->hnA[tid] = (hA - muA) * rsqrtf(vaA + 1e-5f) * pg + pbb;
    S->hnB[tid] = (hB - muB) * rsqrtf(vaB + 1e-5f) * pg + pbb;
    __syncthreads();

    if (w < NQ) {
        float pA = 0.f, pB = 0.f;
#pragma unroll
        for (int it = 0; it < 8; it++) {
            int kk = lane + it * 32;
            pA = fmaf(S->hnA[kk], w2r[it], pA);
            pB = fmaf(S->hnB[kk], w2r[it], pB);
        }
#pragma unroll
        for (int o = 16; o > 0; o >>= 1) {
            pA += __shfl_down_sync(~0u, pA, o);
            pB += __shfl_down_sync(~0u, pB, o);
        }
        if (lane == 0) {
            float bw = b2[w];
            float zA = tanhf(pA + bw), zB = tanhf(pB + bw);
            float snA, cnA, snB, cnB;
            sincosf(PI_F * zA, &snA, &cnA);
            sincosf(PI_F * zB, &snB, &cnB);
            S->tqA[w*3] = 1.f; S->tqA[w*3+1] = LAM1 * snA; S->tqA[w*3+2] = LAM1 * cnA;
            S->tqB[w*3] = 1.f; S->tqB[w*3+1] = LAM1 * snB; S->tqB[w*3+2] = LAM1 * cnB;
        }
    }
    __syncthreads();

    if (tid < 27) {
        int d0 = tid % 3, d1 = (tid / 3) % 3, d2 = tid / 9;
        S->ploA[tid] = S->tqA[d0]     * S->tqA[3 + d1]  * S->tqA[6 + d2];
        S->phiA[tid] = S->tqA[9 + d0] * S->tqA[12 + d1] * S->tqA[15 + d2];
        S->ploB[tid] = S->tqB[d0]     * S->tqB[3 + d1]  * S->tqB[6 + d2];
        S->phiB[tid] = S->tqB[9 + d0] * S->tqB[12 + d1] * S->tqB[15 + d2];
    }
    __syncthreads();

    float accA[NQ] = {0,0,0,0,0,0}, accB[NQ] = {0,0,0,0,0,0};
#pragma unroll
    for (int j = 0; j < 3; j++) {
        int ss = tid + j * 256;
        int sc = (ss < 729) ? ss : 0;      // padded table rows are zero
        int lo = sc % 27, hi = sc / 27;
        float prA = S->ploA[lo] * S->phiA[hi];
        float prB = S->ploB[lo] * S->phiB[hi];
        accA[0] = fmaf(prA, tA[j].x, accA[0]); accB[0] = fmaf(prB, tA[j].x, accB[0]);
        accA[1] = fmaf(prA, tA[j].y, accA[1]); accB[1] = fmaf(prB, tA[j].y, accB[1]);
        accA[2] = fmaf(prA, tA[j].z, accA[2]); accB[2] = fmaf(prB, tA[j].z, accB[2]);
        accA[3] = fmaf(prA, tA[j].w, accA[3]); accB[3] = fmaf(prB, tA[j].w, accB[3]);
        accA[4] = fmaf(prA, tB[j].x, accA[4]); accB[4] = fmaf(prB, tB[j].x, accB[4]);
        accA[5] = fmaf(prA, tB[j].y, accA[5]); accB[5] = fmaf(prB, tB[j].y, accB[5]);
    }
#pragma unroll
    for (int k = 0; k < 6; k++) {
        float a = accA[k], b = accB[k];
#pragma unroll
        for (int o = 16; o > 0; o >>= 1) {
            a += __shfl_down_sync(~0u, a, o);
            b += __shfl_down_sync(~0u, b, o);
        }
        if (lane == 0) { S->r6A[w][k] = a; S->r6B[w][k] = b; }
    }
    __syncthreads();
    if (tid < NQ) {
        float t = 0.f;
#pragma unroll
        for (int ww = 0; ww < 8; ww++) t += S->r6A[ww][tid];
        S->evA[tid] = t;
    } else if (tid >= 32 && tid < 32 + NQ) {
        int k = tid - 32;
        float t = 0.f;
#pragma unroll
        for (int ww = 0; ww < 8; ww++) t += S->r6B[ww][k];
        S->evB[k] = t;
    }
    __syncthreads();
    if (tid < 2) {
        float o = bp[tid];
#pragma unroll
        for (int kq = 0; kq < NQ; kq++) o = fmaf(S->evA[kq], Wp[tid*NQ + kq], o);
        out[rA*2 + tid] = o;
    } else if (tid >= 32 && tid < 34) {
        int t2 = tid - 32;
        float o = bp[t2];
#pragma unroll
        for (int kq = 0; kq < NQ; kq++) o = fmaf(S->evB[kq], Wp[t2*NQ + kq], o);
        out[rB*2 + t2] = o;
    }
}

extern "C" void kernel_launch(void* const* d_in, const int* in_sizes, int n_in,
                              void* d_out, int out_size)
{
    const float* x        = (const float*)d_in[0];
    const float* W1       = (const float*)d_in[1];
    const float* b1       = (const float*)d_in[2];
    const float* ln_g     = (const float*)d_in[3];
    const float* ln_b     = (const float*)d_in[4];
    const float* W2       = (const float*)d_in[5];
    const float* b2       = (const float*)d_in[6];
    const float* shared_w = (const float*)d_in[7];
    const float* task_w   = (const float*)d_in[8];
    const float* Wp       = (const float*)d_in[9];
    const float* bp       = (const float*)d_in[10];
    float* out = (float*)d_out;

    kall<<<GRID, 256>>>(x, W1, shared_w, task_w, b1, ln_g, ln_b, W2, b2, Wp, bp, out);
}

// round 11
// speedup vs baseline: 1.0625x; 1.0625x over previous
#include <cuda_runtime.h>
#include <math.h>

#define NQ    6
#define BATCH 256
#define HID   256
#define INP   784
#define KS    8
#define LAM1  0.9986666666666667f
#define LAM2  0.9866666666666667f
#define LAM12 (LAM1*LAM2)
#define PI_F  3.14159265358979323846f
#define NPTM  6
#define GEMM_BLOCKS 128
#define SMEM_DYN 51200

typedef unsigned long long u64;

__device__ float g_hp[KS * BATCH * HID];   // K-split partial GEMM outputs (2MB)
__device__ float g_Tct[768 * 8];           // evolved observables, [term][obs] zero-padded

// ---------- compile-time tables ----------
struct alignas(16) Tabs {
    short ring[3][4096];   // signed permutation: tg | neg<<12
    short s4of[736];       // base-3 index -> base-4 Pauli index (1->X, 2->Z), padded
};

static constexpr unsigned char LUTc[16] = {0,4,11,15, 5,1,14,26, 6,2,29,9, 3,7,8,12};

static constexpr Tabs make_tabs() {
    Tabs T = {};
    for (int r = 1; r <= 3; r++) {
        for (int s = 0; s < 4096; s++) {
            int cur = s, neg = 0;
            for (int i = 5; i >= 0; --i) {
                int c = i, t = (i + r) % 6;
                int a = (cur >> (2*c)) & 3, b = (cur >> (2*t)) & 3;
                int lv = LUTc[a*4 + b];
                cur = (cur & ~((3 << (2*c)) | (3 << (2*t))))
                    | ((lv & 3) << (2*c)) | (((lv >> 2) & 3) << (2*t));
                neg ^= lv >> 4;
            }
            T.ring[r-1][s] = (short)(cur | (neg << 12));
        }
    }
    for (int s = 0; s < 729; s++) {
        int tmp = s, s4 = 0;
        for (int q = 0; q < 6; q++) {
            int dd = tmp % 3; tmp /= 3;
            if (dd == 1) s4 |= 1 << (2*q);
            else if (dd == 2) s4 |= 3 << (2*q);
        }
        T.s4of[s] = (short)s4;
    }
    return T;
}
__device__ constexpr Tabs g_tabs = make_tabs();

__device__ __forceinline__ int PHYS(int s) {
    return s ^ (((s >> 4) & 7) << 2) ^ (((s >> 8) & 1) << 4);
}

__device__ __forceinline__ void ffma2(u64& d, u64 a, u64 b) {
    asm("fma.rn.f32x2 %0, %1, %2, %0;" : "+l"(d) : "l"(a), "l"(b));
}

// ---------- PTM passes ----------
__device__ __forceinline__ void rotAB(float* m, const float* A0, const float* A1, int tid)
{
    float4* m4 = reinterpret_cast<float4*>(m);
    const int P = (tid & 7) ^ (((tid >> 4) & 1) << 2);
    float4 v[4];
#pragma unroll
    for (int j = 0; j < 4; j++) v[j] = m4[(4*tid + j) ^ P];
#pragma unroll
    for (int j = 0; j < 4; j++) {
        float x = v[j].y, y = v[j].z, z = v[j].w;
        v[j].y = A0[0]*x + A0[1]*y + A0[2]*z;
        v[j].z = A0[3]*x + A0[4]*y + A0[5]*z;
        v[j].w = A0[6]*x + A0[7]*y + A0[8]*z;
    }
    {
        float4 a = v[1], b = v[2], c = v[3];
        v[1].x = A1[0]*a.x + A1[1]*b.x + A1[2]*c.x;
        v[1].y = A1[0]*a.y + A1[1]*b.y + A1[2]*c.y;
        v[1].z = A1[0]*a.z + A1[1]*b.z + A1[2]*c.z;
        v[1].w = A1[0]*a.w + A1[1]*b.w + A1[2]*c.w;
        v[2].x = A1[3]*a.x + A1[4]*b.x + A1[5]*c.x;
        v[2].y = A1[3]*a.y + A1[4]*b.y + A1[5]*c.y;
        v[2].z = A1[3]*a.z + A1[4]*b.z + A1[5]*c.z;
        v[2].w = A1[3]*a.w + A1[4]*b.w + A1[5]*c.w;
        v[3].x = A1[6]*a.x + A1[7]*b.x + A1[8]*c.x;
        v[3].y = A1[6]*a.y + A1[7]*b.y + A1[8]*c.y;
        v[3].z = A1[6]*a.z + A1[7]*b.z + A1[8]*c.z;
        v[3].w = A1[6]*a.w + A1[7]*b.w + A1[8]*c.w;
    }
#pragma unroll
    for (int j = 0; j < 4; j++) m4[(4*tid + j) ^ P] = v[j];
    __syncthreads();
}

__device__ __forceinline__ void rot2dig(float v[16], const float* Alo, const float* Ahi)
{
#pragma unroll
    for (int g = 0; g < 4; g++) {
        float x = v[g*4+1], y = v[g*4+2], z = v[g*4+3];
        v[g*4+1] = Alo[0]*x + Alo[1]*y + Alo[2]*z;
        v[g*4+2] = Alo[3]*x + Alo[4]*y + Alo[5]*z;
        v[g*4+3] = Alo[6]*x + Alo[7]*y + Alo[8]*z;
    }
#pragma unroll
    for (int c = 0; c < 4; c++) {
        float x = v[c+4], y = v[c+8], z = v[c+12];
        v[c+4]  = Ahi[0]*x + Ahi[1]*y + Ahi[2]*z;
        v[c+8]  = Ahi[3]*x + Ahi[4]*y + Ahi[5]*z;
        v[c+12] = Ahi[6]*x + Ahi[7]*y + Ahi[8]*z;
    }
}

__device__ __forceinline__ void rotCD(float* m, const float* A2, const float* A3, int tid)
{
    const int lo = tid & 15, hi = (tid >> 4) << 8;
    float v[16];
#pragma unroll
    for (int e = 0; e < 16; e++) v[e] = m[PHYS(hi | (e << 4) | lo)];
    rot2dig(v, A2, A3);
#pragma unroll
    for (int e = 0; e < 16; e++) m[PHYS(hi | (e << 4) | lo)] = v[e];
    __syncthreads();
}

__device__ __forceinline__ void rotEF(float* m, const float* A4, const float* A5, int tid,
                                      const short* ring, bool dep)
{
    float v[16];
#pragma unroll
    for (int e = 0; e < 16; e++) v[e] = m[PHYS((e << 8) | tid)];
    rot2dig(v, A4, A5);
    if (ring) {
        __syncthreads();
#pragma unroll
        for (int e = 0; e < 16; e++) {
            int s = (e << 8) | tid;
            float val = v[e];
            if (dep) {
                float sc = 1.f;
#pragma unroll
                for (int q = 0; q < 6; q++)
                    if ((s >> (2*q)) & 3) sc *= (q < 5) ? LAM12 : LAM1;
                val *= sc;
            }
            int tg = ring[s];
            m[PHYS(tg & 4095)] = (tg & 4096) ? -val : val;
        }
    } else {
#pragma unroll
        for (int e = 0; e < 16; e++) m[PHYS((e << 8) | tid)] = v[e];
    }
    __syncthreads();
}

// ---------- kernel 1: PTM evolution (blocks 0..5) + 64x64 f32x2 GEMM (6..133) ----------
__global__ void __launch_bounds__(256) k1(const float* __restrict__ x, const float* __restrict__ W1,
                                          const float* __restrict__ sw, const float* __restrict__ tw)
{
    extern __shared__ __align__(16) char su[];
    const int tid = threadIdx.x;
    const int blk = blockIdx.x;
    const int lane = tid & 31, wrp = tid >> 5;

    if (blk < NPTM) {
        float* m = reinterpret_cast<float*>(su);
        short* rtab = reinterpret_cast<short*>(su + 16384);             // [3][4096]
        float (*mats)[10] = reinterpret_cast<float(*)[10]>(su + 41216); // [30][10]

        {
            const uint4* srcT = reinterpret_cast<const uint4*>(&g_tabs.ring[0][0]);
            uint4* dstT = reinterpret_cast<uint4*>(rtab);
#pragma unroll
            for (int i = 0; i < 6; i++) dstT[tid + i*256] = srcT[tid + i*256];
        }
        if (tid < 30) {
            const float* wsrc = (tid < 18) ? (sw + tid*3) : (tw + (tid - 18)*3);
            float sp, cp, st, ct, sw_, cw_;
            sincosf(wsrc[0], &sp, &cp);
            sincosf(wsrc[1], &st, &ct);
            sincosf(wsrc[2], &sw_, &cw_);
            mats[tid][0] =  cp*ct*cw_ - sp*sw_;
            mats[tid][1] =  cp*ct*sw_ + sp*cw_;
            mats[tid][2] = -cp*st;
            mats[tid][3] = -sp*ct*cw_ - cp*sw_;
            mats[tid][4] = -sp*ct*sw_ + cp*cw_;
            mats[tid][5] =  sp*st;
            mats[tid][6] =  st*cw_;
            mats[tid][7] =  st*sw_;
            mats[tid][8] =  ct;
        }
        const int k = blk;
#pragma unroll
        for (int e = 0; e < 16; e++) m[PHYS((e << 8) | tid)] = 0.f;
        __syncthreads();
        if (tid == 0) {
            int tg = g_tabs.ring[1][3 << (2*k)];    // first ring (r=2) applied analytically
            m[PHYS(tg & 4095)] = (tg & 4096) ? -LAM1 : LAM1;
        }
        __syncthreads();

        rotAB(m, mats[24], mats[25], tid);
        rotCD(m, mats[26], mats[27], tid);
        rotEF(m, mats[28], mats[29], tid, rtab + 0*4096, false);   // + R1
        rotAB(m, mats[18], mats[19], tid);
        rotCD(m, mats[20], mats[21], tid);
        rotEF(m, mats[22], mats[23], tid, rtab + 2*4096, true);    // + dep + R3
        rotAB(m, mats[12], mats[13], tid);
        rotCD(m, mats[14], mats[15], tid);
        rotEF(m, mats[16], mats[17], tid, rtab + 1*4096, false);   // + R2
        rotAB(m, mats[6],  mats[7],  tid);
        rotCD(m, mats[8],  mats[9],  tid);
        rotEF(m, mats[10], mats[11], tid, rtab + 0*4096, false);   // + R1
        rotAB(m, mats[0],  mats[1],  tid);
        rotCD(m, mats[2],  mats[3],  tid);
        rotEF(m, mats[4],  mats[5],  tid, (const short*)0, false);

        for (int i = tid; i < 768; i += 256)
            g_Tct[i*8 + k] = (i < 729) ? m[PHYS((int)g_tabs.s4of[i])] : 0.f;
    } else {
        const int g    = blk - NPTM;
        const int rowT = g >> 5;            // 0..3 : 64-row tiles
        const int colT = (g >> 3) & 3;      // 0..3 : 64-col tiles
        const int kp   = g & 7;             // 0..7 : 98-K slices
        const int row0 = rowT * 64, col0 = colT * 64;

        float* ws = reinterpret_cast<float*>(su);            // [64][100]
        float* xs = reinterpret_cast<float*>(su + 25600);    // [64][100]

        const float2* W1_2 = reinterpret_cast<const float2*>(W1);
        const float2* x_2  = reinterpret_cast<const float2*>(x);
        const int kof = kp * 49;            // in float2 units

        // stage W tile (64 cols x 98 k) and x tile (64 rows x 98 k), pad to 100
        for (int idx = tid; idx < 64*49; idx += 256) {
            int c = idx / 49, j2 = idx - c*49;
            float2 wv = W1_2[(col0 + c)*392 + kof + j2];
            ws[c*100 + 2*j2]     = wv.x;
            ws[c*100 + 2*j2 + 1] = wv.y;
            float2 xv = x_2[(row0 + c)*392 + kof + j2];
            xs[c*100 + 2*j2]     = xv.x;
            xs[c*100 + 2*j2 + 1] = xv.y;
        }
        if (tid < 128) {
            int c = tid >> 1, o = 98 + (tid & 1);
            ws[c*100 + o] = 0.f;
            xs[c*100 + o] = 0.f;
        }
        __syncthreads();

        // thread: 8 rows (warp-owned, broadcast) x 2 cols (lane, lane+32)
        const ulonglong2* wA = reinterpret_cast<const ulonglong2*>(ws + lane*100);
        const ulonglong2* wB = reinterpret_cast<const ulonglong2*>(ws + (lane + 32)*100);
        const float* xrow = xs + (wrp * 8) * 100;

        u64 acc[8][2];
#pragma unroll
        for (int r = 0; r < 8; r++) { acc[r][0] = 0ull; acc[r][1] = 0ull; }

#pragma unroll 5
        for (int j = 0; j < 25; j++) {
            ulonglong2 wa = wA[j];
            ulonglong2 wb = wB[j];
#pragma unroll
            for (int r = 0; r < 8; r++) {
                ulonglong2 xv = *reinterpret_cast<const ulonglong2*>(xrow + r*100 + 4*j);
                ffma2(acc[r][0], xv.x, wa.x);
                ffma2(acc[r][0], xv.y, wa.y);
                ffma2(acc[r][1], xv.x, wb.x);
                ffma2(acc[r][1], xv.y, wb.y);
            }
        }
#pragma unroll
        for (int r = 0; r < 8; r++) {
            int row = row0 + wrp*8 + r;
            float2 a0 = *reinterpret_cast<float2*>(&acc[r][0]);
            float2 a1 = *reinterpret_cast<float2*>(&acc[r][1]);
            g_hp[kp*65536 + row*256 + col0 + lane]      = a0.x + a0.y;
            g_hp[kp*65536 + row*256 + col0 + 32 + lane] = a1.x + a1.y;
        }
    }
}

// ---------- kernel 2: 2 rows/block; bias/ReLU + LN + W2/tanh + quantum eval + projection ----------
__global__ void __launch_bounds__(256) k2(const float* __restrict__ b1v,
                                          const float* __restrict__ lng, const float* __restrict__ lnb,
                                          const float* __restrict__ W2, const float* __restrict__ b2,
                                          const float* __restrict__ Wp, const float* __restrict__ bp,
                                          float* __restrict__ out)
{
    __shared__ float hnA[HID], hnB[HID];
    __shared__ float4 red[8];
    __shared__ float tqA[18], tqB[18];
    __shared__ float ploA[27], phiA[27], ploB[27], phiB[27];
    __shared__ float r6A[8][6], r6B[8][6];
    __shared__ float evA[NQ], evB[NQ];

    const int tid = threadIdx.x;
    const int lane = tid & 31, w = tid >> 5;
    const int rA = blockIdx.x * 2, rB = rA + 1;

    const float4* Tct4 = reinterpret_cast<const float4*>(g_Tct);
    float4 tA[3], tB[3];
#pragma unroll
    for (int j = 0; j < 3; j++) {
        int ss = tid + j * 256;
        tA[j] = Tct4[ss*2];
        tB[j] = Tct4[ss*2 + 1];
    }
    float w2r[8];
    if (w < NQ) {
#pragma unroll
        for (int it = 0; it < 8; it++) w2r[it] = W2[w*256 + lane + it*32];
    }

    float hA = b1v[tid], hB = hA;
#pragma unroll
    for (int p = 0; p < KS; p++) {
        hA += g_hp[p*65536 + rA*HID + tid];
        hB += g_hp[p*65536 + rB*HID + tid];
    }
    hA = fmaxf(hA, 0.f);
    hB = fmaxf(hB, 0.f);

    float s0 = hA, q0 = hA*hA, s1 = hB, q1 = hB*hB;
#pragma unroll
    for (int o = 16; o > 0; o >>= 1) {
        s0 += __shfl_down_sync(~0u, s0, o);
        q0 += __shfl_down_sync(~0u, q0, o);
        s1 += __shfl_down_sync(~0u, s1, o);
        q1 += __shfl_down_sync(~0u, q1, o);
    }
    if (lane == 0) red[w] = make_float4(s0, q0, s1, q1);
    __syncthreads();
    if (tid < 8) {
        float4 t = red[tid];
#pragma unroll
        for (int o = 4; o > 0; o >>= 1) {
            t.x += __shfl_down_sync(0xffu, t.x, o);
            t.y += __shfl_down_sync(0xffu, t.y, o);
            t.z += __shfl_down_sync(0xffu, t.z, o);
            t.w += __shfl_down_sync(0xffu, t.w, o);
        }
        if (tid == 0) red[0] = t;
    }
    __syncthreads();
    float4 R = red[0];
    float muA = R.x * (1.f/256.f), vaA = R.y * (1.f/256.f) - muA*muA;
    float muB = R.z * (1.f/256.f), vaB = R.w * (1.f/256.f) - muB*muB;
    float gg = lng[tid], bb = lnb[tid];
    hnA[tid] = (hA - muA) * rsqrtf(vaA + 1e-5f) * gg + bb;
    hnB[tid] = (hB - muB) * rsqrtf(vaB + 1e-5f) * gg + bb;
    __syncthreads();

    if (w < NQ) {
        float pA = 0.f, pB = 0.f;
#pragma unroll
        for (int it = 0; it < 8; it++) {
            int kk = lane + it * 32;
            pA = fmaf(hnA[kk], w2r[it], pA);
            pB = fmaf(hnB[kk], w2r[it], pB);
        }
#pragma unroll
        for (int o = 16; o > 0; o >>= 1) {
            pA += __shfl_down_sync(~0u, pA, o);
            pB += __shfl_down_sync(~0u, pB, o);
        }
        if (lane == 0) {
            float bw = b2[w];
            float zA = tanhf(pA + bw), zB = tanhf(pB + bw);
            float snA, cnA, snB, cnB;
            sincosf(PI_F * zA, &snA, &cnA);
            sincosf(PI_F * zB, &snB, &cnB);
            tqA[w*3] = 1.f; tqA[w*3+1] = LAM1 * snA; tqA[w*3+2] = LAM1 * cnA;
            tqB[w*3] = 1.f; tqB[w*3+1] = LAM1 * snB; tqB[w*3+2] = LAM1 * cnB;
        }
    }
    __syncthreads();

    if (tid < 27) {
        int d0 = tid % 3, d1 = (tid / 3) % 3, d2 = tid / 9;
        ploA[tid] = tqA[d0]     * tqA[3 + d1]  * tqA[6 + d2];
        phiA[tid] = tqA[9 + d0] * tqA[12 + d1] * tqA[15 + d2];
        ploB[tid] = tqB[d0]     * tqB[3 + d1]  * tqB[6 + d2];
        phiB[tid] = tqB[9 + d0] * tqB[12 + d1] * tqB[15 + d2];
    }
    __syncthreads();

    float accA[NQ] = {0,0,0,0,0,0}, accB[NQ] = {0,0,0,0,0,0};
#pragma unroll
    for (int j = 0; j < 3; j++) {
        int ss = tid + j * 256;
        int sc = (ss < 729) ? ss : 0;      // padded table rows are zero
        int lo = sc % 27, hi = sc / 27;
        float prA = ploA[lo] * phiA[hi];
        float prB = ploB[lo] * phiB[hi];
        accA[0] = fmaf(prA, tA[j].x, accA[0]); accB[0] = fmaf(prB, tA[j].x, accB[0]);
        accA[1] = fmaf(prA, tA[j].y, accA[1]); accB[1] = fmaf(prB, tA[j].y, accB[1]);
        accA[2] = fmaf(prA, tA[j].z, accA[2]); accB[2] = fmaf(prB, tA[j].z, accB[2]);
        accA[3] = fmaf(prA, tA[j].w, accA[3]); accB[3] = fmaf(prB, tA[j].w, accB[3]);
        accA[4] = fmaf(prA, tB[j].x, accA[4]); accB[4] = fmaf(prB, tB[j].x, accB[4]);
        accA[5] = fmaf(prA, tB[j].y, accA[5]); accB[5] = fmaf(prB, tB[j].y, accB[5]);
    }
#pragma unroll
    for (int k = 0; k < 6; k++) {
        float a = accA[k], b = accB[k];
#pragma unroll
        for (int o = 16; o > 0; o >>= 1) {
            a += __shfl_down_sync(~0u, a, o);
            b += __shfl_down_sync(~0u, b, o);
        }
        if (lane == 0) { r6A[w][k] = a; r6B[w][k] = b; }
    }
    __syncthreads();
    if (tid < NQ) {
        float t = 0.f;
#pragma unroll
        for (int ww = 0; ww < 8; ww++) t += r6A[ww][tid];
        evA[tid] = t;
    } else if (tid >= 32 && tid < 32 + NQ) {
        int k = tid - 32;
        float t = 0.f;
#pragma unroll
        for (int ww = 0; ww < 8; ww++) t += r6B[ww][k];
        evB[k] = t;
    }
    __syncthreads();
    if (tid < 2) {
        float o = bp[tid];
#pragma unroll
        for (int kq = 0; kq < NQ; kq++) o = fmaf(evA[kq], Wp[tid*NQ + kq], o);
        out[rA*2 + tid] = o;
    } else if (tid >= 32 && tid < 34) {
        int t2 = tid - 32;
        float o = bp[t2];
#pragma unroll
        for (int kq = 0; kq < NQ; kq++) o = fmaf(evB[kq], Wp[t2*NQ + kq], o);
        out[rB*2 + t2] = o;
    }
}

extern "C" void kernel_launch(void* const* d_in, const int* in_sizes, int n_in,
                              void* d_out, int out_size)
{
    const float* x        = (const float*)d_in[0];
    const float* W1       = (const float*)d_in[1];
    const float* b1       = (const float*)d_in[2];
    const float* ln_g     = (const float*)d_in[3];
    const float* ln_b     = (const float*)d_in[4];
    const float* W2       = (const float*)d_in[5];
    const float* b2       = (const float*)d_in[6];
    const float* shared_w = (const float*)d_in[7];
    const float* task_w   = (const float*)d_in[8];
    const float* Wp       = (const float*)d_in[9];
    const float* bp       = (const float*)d_in[10];
    float* out = (float*)d_out;

    static int attr_set = 0;
    if (!attr_set) {
        cudaFuncSetAttribute(k1, cudaFuncAttributeMaxDynamicSharedMemorySize, SMEM_DYN);
        attr_set = 1;
    }

    k1<<<NPTM + GEMM_BLOCKS, 256, SMEM_DYN>>>(x, W1, shared_w, task_w);
    k2<<<BATCH / 2, 256>>>(b1, ln_g, ln_b, W2, b2, Wp, bp, out);
}

// round 12
// speedup vs baseline: 1.2091x; 1.1379x over previous
#include <cuda_runtime.h>
#include <math.h>

#define NQ    6
#define BATCH 256
#define HID   256
#define INP   784
#define KS    8
#define LAM1  0.9986666666666667f
#define LAM2  0.9866666666666667f
#define LAM12 (LAM1*LAM2)
#define PI_F  3.14159265358979323846f
#define NPTM  6
#define GEMM_BLOCKS 128
#define SMEM_DYN 51200

typedef unsigned long long u64;

__device__ float g_hp[KS * BATCH * HID];   // K-split partial GEMM outputs (2MB)
__device__ float g_Tct[768 * 8];           // evolved observables, [term][obs] zero-padded

// ---------- compile-time tables ----------
struct alignas(16) Tabs {
    short ring[3][4096];   // signed permutation: tg | neg<<12
    short s4of[736];       // base-3 index -> base-4 Pauli index (1->X, 2->Z), padded
};

static constexpr unsigned char LUTc[16] = {0,4,11,15, 5,1,14,26, 6,2,29,9, 3,7,8,12};

static constexpr Tabs make_tabs() {
    Tabs T = {};
    for (int r = 1; r <= 3; r++) {
        for (int s = 0; s < 4096; s++) {
            int cur = s, neg = 0;
            for (int i = 5; i >= 0; --i) {
                int c = i, t = (i + r) % 6;
                int a = (cur >> (2*c)) & 3, b = (cur >> (2*t)) & 3;
                int lv = LUTc[a*4 + b];
                cur = (cur & ~((3 << (2*c)) | (3 << (2*t))))
                    | ((lv & 3) << (2*c)) | (((lv >> 2) & 3) << (2*t));
                neg ^= lv >> 4;
            }
            T.ring[r-1][s] = (short)(cur | (neg << 12));
        }
    }
    for (int s = 0; s < 729; s++) {
        int tmp = s, s4 = 0;
        for (int q = 0; q < 6; q++) {
            int dd = tmp % 3; tmp /= 3;
            if (dd == 1) s4 |= 1 << (2*q);
            else if (dd == 2) s4 |= 3 << (2*q);
        }
        T.s4of[s] = (short)s4;
    }
    return T;
}
__device__ constexpr Tabs g_tabs = make_tabs();

__device__ __forceinline__ int PHYS(int s) {
    return s ^ (((s >> 4) & 7) << 2) ^ (((s >> 8) & 1) << 4);
}

__device__ __forceinline__ void ffma2(u64& d, u64 a, u64 b) {
    asm("fma.rn.f32x2 %0, %1, %2, %0;" : "+l"(d) : "l"(a), "l"(b));
}

// ---------- PTM passes ----------
__device__ __forceinline__ void rotAB(float* m, const float* A0, const float* A1, int tid)
{
    float4* m4 = reinterpret_cast<float4*>(m);
    const int P = (tid & 7) ^ (((tid >> 4) & 1) << 2);
    float4 v[4];
#pragma unroll
    for (int j = 0; j < 4; j++) v[j] = m4[(4*tid + j) ^ P];
#pragma unroll
    for (int j = 0; j < 4; j++) {
        float x = v[j].y, y = v[j].z, z = v[j].w;
        v[j].y = A0[0]*x + A0[1]*y + A0[2]*z;
        v[j].z = A0[3]*x + A0[4]*y + A0[5]*z;
        v[j].w = A0[6]*x + A0[7]*y + A0[8]*z;
    }
    {
        float4 a = v[1], b = v[2], c = v[3];
        v[1].x = A1[0]*a.x + A1[1]*b.x + A1[2]*c.x;
        v[1].y = A1[0]*a.y + A1[1]*b.y + A1[2]*c.y;
        v[1].z = A1[0]*a.z + A1[1]*b.z + A1[2]*c.z;
        v[1].w = A1[0]*a.w + A1[1]*b.w + A1[2]*c.w;
        v[2].x = A1[3]*a.x + A1[4]*b.x + A1[5]*c.x;
        v[2].y = A1[3]*a.y + A1[4]*b.y + A1[5]*c.y;
        v[2].z = A1[3]*a.z + A1[4]*b.z + A1[5]*c.z;
        v[2].w = A1[3]*a.w + A1[4]*b.w + A1[5]*c.w;
        v[3].x = A1[6]*a.x + A1[7]*b.x + A1[8]*c.x;
        v[3].y = A1[6]*a.y + A1[7]*b.y + A1[8]*c.y;
        v[3].z = A1[6]*a.z + A1[7]*b.z + A1[8]*c.z;
        v[3].w = A1[6]*a.w + A1[7]*b.w + A1[8]*c.w;
    }
#pragma unroll
    for (int j = 0; j < 4; j++) m4[(4*tid + j) ^ P] = v[j];
    __syncthreads();
}

__device__ __forceinline__ void rot2dig(float v[16], const float* Alo, const float* Ahi)
{
#pragma unroll
    for (int g = 0; g < 4; g++) {
        float x = v[g*4+1], y = v[g*4+2], z = v[g*4+3];
        v[g*4+1] = Alo[0]*x + Alo[1]*y + Alo[2]*z;
        v[g*4+2] = Alo[3]*x + Alo[4]*y + Alo[5]*z;
        v[g*4+3] = Alo[6]*x + Alo[7]*y + Alo[8]*z;
    }
#pragma unroll
    for (int c = 0; c < 4; c++) {
        float x = v[c+4], y = v[c+8], z = v[c+12];
        v[c+4]  = Ahi[0]*x + Ahi[1]*y + Ahi[2]*z;
        v[c+8]  = Ahi[3]*x + Ahi[4]*y + Ahi[5]*z;
        v[c+12] = Ahi[6]*x + Ahi[7]*y + Ahi[8]*z;
    }
}

__device__ __forceinline__ void rotCD(float* m, const float* A2, const float* A3, int tid)
{
    const int lo = tid & 15, hi = (tid >> 4) << 8;
    float v[16];
#pragma unroll
    for (int e = 0; e < 16; e++) v[e] = m[PHYS(hi | (e << 4) | lo)];
    rot2dig(v, A2, A3);
#pragma unroll
    for (int e = 0; e < 16; e++) m[PHYS(hi | (e << 4) | lo)] = v[e];
    __syncthreads();
}

__device__ __forceinline__ void rotEF(float* m, const float* A4, const float* A5, int tid,
                                      const short* ring, bool dep)
{
    float v[16];
#pragma unroll
    for (int e = 0; e < 16; e++) v[e] = m[PHYS((e << 8) | tid)];
    rot2dig(v, A4, A5);
    if (ring) {
        __syncthreads();
#pragma unroll
        for (int e = 0; e < 16; e++) {
            int s = (e << 8) | tid;
            float val = v[e];
            if (dep) {
                float sc = 1.f;
#pragma unroll
                for (int q = 0; q < 6; q++)
                    if ((s >> (2*q)) & 3) sc *= (q < 5) ? LAM12 : LAM1;
                val *= sc;
            }
            int tg = ring[s];
            m[PHYS(tg & 4095)] = (tg & 4096) ? -val : val;
        }
    } else {
#pragma unroll
        for (int e = 0; e < 16; e++) m[PHYS((e << 8) | tid)] = v[e];
    }
    __syncthreads();
}

// ---------- kernel 1: PTM evolution (blocks 0..5) + 64x64 f32x2 GEMM (6..133) ----------
__global__ void __launch_bounds__(256) k1(const float* __restrict__ x, const float* __restrict__ W1,
                                          const float* __restrict__ sw, const float* __restrict__ tw)
{
    extern __shared__ __align__(16) char su[];
    const int tid = threadIdx.x;
    const int blk = blockIdx.x;
    const int lane = tid & 31, wrp = tid >> 5;

    if (blk < NPTM) {
        float* m = reinterpret_cast<float*>(su);
        short* rtab = reinterpret_cast<short*>(su + 16384);             // [3][4096]
        float (*mats)[10] = reinterpret_cast<float(*)[10]>(su + 41216); // [30][10]

        {
            const uint4* srcT = reinterpret_cast<const uint4*>(&g_tabs.ring[0][0]);
            uint4* dstT = reinterpret_cast<uint4*>(rtab);
#pragma unroll
            for (int i = 0; i < 6; i++) dstT[tid + i*256] = srcT[tid + i*256];
        }
        if (tid < 30) {
            const float* wsrc = (tid < 18) ? (sw + tid*3) : (tw + (tid - 18)*3);
            float sp, cp, st, ct, sw_, cw_;
            sincosf(wsrc[0], &sp, &cp);
            sincosf(wsrc[1], &st, &ct);
            sincosf(wsrc[2], &sw_, &cw_);
            mats[tid][0] =  cp*ct*cw_ - sp*sw_;
            mats[tid][1] =  cp*ct*sw_ + sp*cw_;
            mats[tid][2] = -cp*st;
            mats[tid][3] = -sp*ct*cw_ - cp*sw_;
            mats[tid][4] = -sp*ct*sw_ + cp*cw_;
            mats[tid][5] =  sp*st;
            mats[tid][6] =  st*cw_;
            mats[tid][7] =  st*sw_;
            mats[tid][8] =  ct;
        }
        const int k = blk;
#pragma unroll
        for (int e = 0; e < 16; e++) m[PHYS((e << 8) | tid)] = 0.f;
        __syncthreads();
        if (tid == 0) {
            int tg = g_tabs.ring[1][3 << (2*k)];    // first ring (r=2) applied analytically
            m[PHYS(tg & 4095)] = (tg & 4096) ? -LAM1 : LAM1;
        }
        __syncthreads();

        rotAB(m, mats[24], mats[25], tid);
        rotCD(m, mats[26], mats[27], tid);
        rotEF(m, mats[28], mats[29], tid, rtab + 0*4096, false);   // + R1
        rotAB(m, mats[18], mats[19], tid);
        rotCD(m, mats[20], mats[21], tid);
        rotEF(m, mats[22], mats[23], tid, rtab + 2*4096, true);    // + dep + R3
        rotAB(m, mats[12], mats[13], tid);
        rotCD(m, mats[14], mats[15], tid);
        rotEF(m, mats[16], mats[17], tid, rtab + 1*4096, false);   // + R2
        rotAB(m, mats[6],  mats[7],  tid);
        rotCD(m, mats[8],  mats[9],  tid);
        rotEF(m, mats[10], mats[11], tid, rtab + 0*4096, false);   // + R1
        rotAB(m, mats[0],  mats[1],  tid);
        rotCD(m, mats[2],  mats[3],  tid);
        rotEF(m, mats[4],  mats[5],  tid, (const short*)0, false);

        for (int i = tid; i < 768; i += 256)
            g_Tct[i*8 + k] = (i < 729) ? m[PHYS((int)g_tabs.s4of[i])] : 0.f;
    } else {
        const int g    = blk - NPTM;
        const int rowT = g >> 5;            // 0..3 : 64-row tiles
        const int colT = (g >> 3) & 3;      // 0..3 : 64-col tiles
        const int kp   = g & 7;             // 0..7 : 98-K slices
        const int row0 = rowT * 64, col0 = colT * 64;

        float* ws = reinterpret_cast<float*>(su);            // [64][100]
        float* xs = reinterpret_cast<float*>(su + 25600);    // [64][100]

        const float2* W1_2 = reinterpret_cast<const float2*>(W1);
        const float2* x_2  = reinterpret_cast<const float2*>(x);
        const int kof = kp * 49;            // in float2 units

        for (int idx = tid; idx < 64*49; idx += 256) {
            int c = idx / 49, j2 = idx - c*49;
            float2 wv = W1_2[(col0 + c)*392 + kof + j2];
            ws[c*100 + 2*j2]     = wv.x;
            ws[c*100 + 2*j2 + 1] = wv.y;
            float2 xv = x_2[(row0 + c)*392 + kof + j2];
            xs[c*100 + 2*j2]     = xv.x;
            xs[c*100 + 2*j2 + 1] = xv.y;
        }
        if (tid < 128) {
            int c = tid >> 1, o = 98 + (tid & 1);
            ws[c*100 + o] = 0.f;
            xs[c*100 + o] = 0.f;
        }
        __syncthreads();

        const ulonglong2* wA = reinterpret_cast<const ulonglong2*>(ws + lane*100);
        const ulonglong2* wB = reinterpret_cast<const ulonglong2*>(ws + (lane + 32)*100);
        const float* xrow = xs + (wrp * 8) * 100;

        u64 acc[8][2];
#pragma unroll
        for (int r = 0; r < 8; r++) { acc[r][0] = 0ull; acc[r][1] = 0ull; }

#pragma unroll 5
        for (int j = 0; j < 25; j++) {
            ulonglong2 wa = wA[j];
            ulonglong2 wb = wB[j];
#pragma unroll
            for (int r = 0; r < 8; r++) {
                ulonglong2 xv = *reinterpret_cast<const ulonglong2*>(xrow + r*100 + 4*j);
                ffma2(acc[r][0], xv.x, wa.x);
                ffma2(acc[r][0], xv.y, wa.y);
                ffma2(acc[r][1], xv.x, wb.x);
                ffma2(acc[r][1], xv.y, wb.y);
            }
        }
#pragma unroll
        for (int r = 0; r < 8; r++) {
            int row = row0 + wrp*8 + r;
            float2 a0 = *reinterpret_cast<float2*>(&acc[r][0]);
            float2 a1 = *reinterpret_cast<float2*>(&acc[r][1]);
            g_hp[kp*65536 + row*256 + col0 + lane]      = a0.x + a0.y;
            g_hp[kp*65536 + row*256 + col0 + 32 + lane] = a1.x + a1.y;
        }
    }
#if __CUDA_ARCH__ >= 900
    cudaTriggerProgrammaticLaunchCompletion();
#endif
}

// ---------- kernel 2 (PDL secondary): params prefetched before grid-dependency sync ----------
__global__ void __launch_bounds__(256) k2(const float* __restrict__ b1v,
                                          const float* __restrict__ lng, const float* __restrict__ lnb,
                                          const float* __restrict__ W2, const float* __restrict__ b2,
                                          const float* __restrict__ Wp, const float* __restrict__ bp,
                                          float* __restrict__ out)
{
    __shared__ float hnA[HID], hnB[HID];
    __shared__ float4 red[8];
    __shared__ float tqA[18], tqB[18];
    __shared__ float ploA[27], phiA[27], ploB[27], phiB[27];
    __shared__ float r6A[8][6], r6B[8][6];
    __shared__ float evA[NQ], evB[NQ];

    const int tid = threadIdx.x;
    const int lane = tid & 31, w = tid >> 5;
    const int rA = blockIdx.x * 2, rB = rA + 1;

    // ---- k1-independent prefetch (overlaps k1 execution under PDL) ----
    const float pb1 = b1v[tid], pg = lng[tid], pbb = lnb[tid];
    float w2r[8];
    float bw = 0.f;
    if (w < NQ) {
#pragma unroll
        for (int it = 0; it < 8; it++) w2r[it] = W2[w*256 + lane + it*32];
        bw = b2[w];
    }
    float wp0 = 0.f, wp1 = 0.f, bp0 = 0.f;
    if (tid < 12) wp0 = Wp[tid];
    if (tid < 2)  bp0 = bp[tid];
    (void)wp1;

#if __CUDA_ARCH__ >= 900
    cudaGridDependencySynchronize();
#endif

    // ---- k1-dependent part ----
    const float4* Tct4 = reinterpret_cast<const float4*>(g_Tct);
    float4 tA[3], tB[3];
#pragma unroll
    for (int j = 0; j < 3; j++) {
        int ss = tid + j * 256;
        tA[j] = Tct4[ss*2];
        tB[j] = Tct4[ss*2 + 1];
    }

    float hA = pb1, hB = pb1;
#pragma unroll
    for (int p = 0; p < KS; p++) {
        hA += g_hp[p*65536 + rA*HID + tid];
        hB += g_hp[p*65536 + rB*HID + tid];
    }
    hA = fmaxf(hA, 0.f);
    hB = fmaxf(hB, 0.f);

    float s0 = hA, q0 = hA*hA, s1 = hB, q1 = hB*hB;
#pragma unroll
    for (int o = 16; o > 0; o >>= 1) {
        s0 += __shfl_down_sync(~0u, s0, o);
        q0 += __shfl_down_sync(~0u, q0, o);
        s1 += __shfl_down_sync(~0u, s1, o);
        q1 += __shfl_down_sync(~0u, q1, o);
    }
    if (lane == 0) red[w] = make_float4(s0, q0, s1, q1);
    __syncthreads();
    if (tid < 8) {
        float4 t = red[tid];
#pragma unroll
        for (int o = 4; o > 0; o >>= 1) {
            t.x += __shfl_down_sync(0xffu, t.x, o);
            t.y += __shfl_down_sync(0xffu, t.y, o);
            t.z += __shfl_down_sync(0xffu, t.z, o);
            t.w += __shfl_down_sync(0xffu, t.w, o);
        }
        if (tid == 0) red[0] = t;
    }
    __syncthreads();
    float4 R = red[0];
    float muA = R.x * (1.f/256.f), vaA = R.y * (1.f/256.f) - muA*muA;
    float muB = R.z * (1.f/256.f), vaB = R.w * (1.f/256.f) - muB*muB;
    hnA[tid] = (hA - muA) * rsqrtf(vaA + 1e-5f) * pg + pbb;
    hnB[tid] = (hB - muB) * rsqrtf(vaB + 1e-5f) * pg + pbb;
    __syncthreads();

    if (w < NQ) {
        float pA = 0.f, pB = 0.f;
#pragma unroll
        for (int it = 0; it < 8; it++) {
            int kk = lane + it * 32;
            pA = fmaf(hnA[kk], w2r[it], pA);
            pB = fmaf(hnB[kk], w2r[it], pB);
        }
#pragma unroll
        for (int o = 16; o > 0; o >>= 1) {
            pA += __shfl_down_sync(~0u, pA, o);
            pB += __shfl_down_sync(~0u, pB, o);
        }
        if (lane == 0) {
            float zA = tanhf(pA + bw), zB = tanhf(pB + bw);
            float snA, cnA, snB, cnB;
            sincosf(PI_F * zA, &snA, &cnA);
            sincosf(PI_F * zB, &snB, &cnB);
            tqA[w*3] = 1.f; tqA[w*3+1] = LAM1 * snA; tqA[w*3+2] = LAM1 * cnA;
            tqB[w*3] = 1.f; tqB[w*3+1] = LAM1 * snB; tqB[w*3+2] = LAM1 * cnB;
        }
    }
    __syncthreads();

    if (tid < 27) {
        int d0 = tid % 3, d1 = (tid / 3) % 3, d2 = tid / 9;
        ploA[tid] = tqA[d0]     * tqA[3 + d1]  * tqA[6 + d2];
        phiA[tid] = tqA[9 + d0] * tqA[12 + d1] * tqA[15 + d2];
        ploB[tid] = tqB[d0]     * tqB[3 + d1]  * tqB[6 + d2];
        phiB[tid] = tqB[9 + d0] * tqB[12 + d1] * tqB[15 + d2];
    }
    __syncthreads();

    float accA[NQ] = {0,0,0,0,0,0}, accB[NQ] = {0,0,0,0,0,0};
#pragma unroll
    for (int j = 0; j < 3; j++) {
        int ss = tid + j * 256;
        int sc = (ss < 729) ? ss : 0;      // padded table rows are zero
        int lo = sc % 27, hi = sc / 27;
        float prA = ploA[lo] * phiA[hi];
        float prB = ploB[lo] * phiB[hi];
        accA[0] = fmaf(prA, tA[j].x, accA[0]); accB[0] = fmaf(prB, tA[j].x, accB[0]);
        accA[1] = fmaf(prA, tA[j].y, accA[1]); accB[1] = fmaf(prB, tA[j].y, accB[1]);
        accA[2] = fmaf(prA, tA[j].z, accA[2]); accB[2] = fmaf(prB, tA[j].z, accB[2]);
        accA[3] = fmaf(prA, tA[j].w, accA[3]); accB[3] = fmaf(prB, tA[j].w, accB[3]);
        accA[4] = fmaf(prA, tB[j].x, accA[4]); accB[4] = fmaf(prB, tB[j].x, accB[4]);
        accA[5] = fmaf(prA, tB[j].y, accA[5]); accB[5] = fmaf(prB, tB[j].y, accB[5]);
    }
#pragma unroll
    for (int k = 0; k < 6; k++) {
        float a = accA[k], b = accB[k];
#pragma unroll
        for (int o = 16; o > 0; o >>= 1) {
            a += __shfl_down_sync(~0u, a, o);
            b += __shfl_down_sync(~0u, b, o);
        }
        if (lane == 0) { r6A[w][k] = a; r6B[w][k] = b; }
    }
    __syncthreads();
    if (tid < NQ) {
        float t = 0.f;
#pragma unroll
        for (int ww = 0; ww < 8; ww++) t += r6A[ww][tid];
        evA[tid] = t;
    } else if (tid >= 32 && tid < 32 + NQ) {
        int k = tid - 32;
        float t = 0.f;
#pragma unroll
        for (int ww = 0; ww < 8; ww++) t += r6B[ww][k];
        evB[k] = t;
    }
    __syncthreads();
    if (tid < 2) {
        float o = bp0;
#pragma unroll
        for (int kq = 0; kq < NQ; kq++) o = fmaf(evA[kq], Wp[tid*NQ + kq], o);
        out[rA*2 + tid] = o;
    } else if (tid >= 32 && tid < 34) {
        int t2 = tid - 32;
        float o = bp[t2];
#pragma unroll
        for (int kq = 0; kq < NQ; kq++) o = fmaf(evB[kq], Wp[t2*NQ + kq], o);
        out[rB*2 + t2] = o;
    }
    (void)wp0;
}

extern "C" void kernel_launch(void* const* d_in, const int* in_sizes, int n_in,
                              void* d_out, int out_size)
{
    const float* x        = (const float*)d_in[0];
    const float* W1       = (const float*)d_in[1];
    const float* b1       = (const float*)d_in[2];
    const float* ln_g     = (const float*)d_in[3];
    const float* ln_b     = (const float*)d_in[4];
    const float* W2       = (const float*)d_in[5];
    const float* b2       = (const float*)d_in[6];
    const float* shared_w = (const float*)d_in[7];
    const float* task_w   = (const float*)d_in[8];
    const float* Wp       = (const float*)d_in[9];
    const float* bp       = (const float*)d_in[10];
    float* out = (float*)d_out;

    cudaFuncSetAttribute(k1, cudaFuncAttributeMaxDynamicSharedMemorySize, SMEM_DYN);

    k1<<<NPTM + GEMM_BLOCKS, 256, SMEM_DYN>>>(x, W1, shared_w, task_w);

    cudaLaunchConfig_t cfg = {};
    cfg.gridDim  = dim3(BATCH / 2, 1, 1);
    cfg.blockDim = dim3(256, 1, 1);
    cfg.dynamicSmemBytes = 0;
    cudaLaunchAttribute attrs[1];
    attrs[0].id = cudaLaunchAttributeProgrammaticStreamSerialization;
    attrs[0].val.programmaticStreamSerializationAllowed = 1;
    cfg.attrs = attrs;
    cfg.numAttrs = 1;
    cudaLaunchKernelEx(&cfg, k2, b1, ln_g, ln_b, W2, b2, Wp, bp, out);
}

// round 13
// speedup vs baseline: 1.2117x; 1.0022x over previous
#include <cuda_runtime.h>
#include <math.h>

#define NQ    6
#define BATCH 256
#define HID   256
#define INP   784
#define KS    8
#define LAM1  0.9986666666666667f
#define LAM2  0.9866666666666667f
#define LAM12 (LAM1*LAM2)
#define PI_F  3.14159265358979323846f
#define NPTM  6
#define GEMM_BLOCKS 128
#define SMEM_DYN 51200

typedef unsigned long long u64;

__device__ float g_hp[KS * BATCH * HID];   // K-split partial GEMM outputs (2MB)
__device__ float g_Tct[768 * 8];           // evolved observables, [term][obs] zero-padded

// ---------- compile-time tables ----------
struct alignas(16) Tabs {
    short ring[3][4096];   // signed permutation: tg | neg<<12
    short s4of[736];       // base-3 index -> base-4 Pauli index (1->X, 2->Z), padded
};

static constexpr unsigned char LUTc[16] = {0,4,11,15, 5,1,14,26, 6,2,29,9, 3,7,8,12};

static constexpr Tabs make_tabs() {
    Tabs T = {};
    for (int r = 1; r <= 3; r++) {
        for (int s = 0; s < 4096; s++) {
            int cur = s, neg = 0;
            for (int i = 5; i >= 0; --i) {
                int c = i, t = (i + r) % 6;
                int a = (cur >> (2*c)) & 3, b = (cur >> (2*t)) & 3;
                int lv = LUTc[a*4 + b];
                cur = (cur & ~((3 << (2*c)) | (3 << (2*t))))
                    | ((lv & 3) << (2*c)) | (((lv >> 2) & 3) << (2*t));
                neg ^= lv >> 4;
            }
            T.ring[r-1][s] = (short)(cur | (neg << 12));
        }
    }
    for (int s = 0; s < 729; s++) {
        int tmp = s, s4 = 0;
        for (int q = 0; q < 6; q++) {
            int dd = tmp % 3; tmp /= 3;
            if (dd == 1) s4 |= 1 << (2*q);
            else if (dd == 2) s4 |= 3 << (2*q);
        }
        T.s4of[s] = (short)s4;
    }
    return T;
}
__device__ constexpr Tabs g_tabs = make_tabs();

__device__ __forceinline__ int PHYS(int s) {
    return s ^ (((s >> 4) & 7) << 2) ^ (((s >> 8) & 1) << 4);
}

__device__ __forceinline__ void ffma2(u64& d, u64 a, u64 b) {
    asm("fma.rn.f32x2 %0, %1, %2, %0;" : "+l"(d) : "l"(a), "l"(b));
}

// ---------- PTM passes ----------
__device__ __forceinline__ void rotAB(float* m, const float* A0, const float* A1, int tid)
{
    float4* m4 = reinterpret_cast<float4*>(m);
    const int P = (tid & 7) ^ (((tid >> 4) & 1) << 2);
    float4 v[4];
#pragma unroll
    for (int j = 0; j < 4; j++) v[j] = m4[(4*tid + j) ^ P];
#pragma unroll
    for (int j = 0; j < 4; j++) {
        float x = v[j].y, y = v[j].z, z = v[j].w;
        v[j].y = A0[0]*x + A0[1]*y + A0[2]*z;
        v[j].z = A0[3]*x + A0[4]*y + A0[5]*z;
        v[j].w = A0[6]*x + A0[7]*y + A0[8]*z;
    }
    {
        float4 a = v[1], b = v[2], c = v[3];
        v[1].x = A1[0]*a.x + A1[1]*b.x + A1[2]*c.x;
        v[1].y = A1[0]*a.y + A1[1]*b.y + A1[2]*c.y;
        v[1].z = A1[0]*a.z + A1[1]*b.z + A1[2]*c.z;
        v[1].w = A1[0]*a.w + A1[1]*b.w + A1[2]*c.w;
        v[2].x = A1[3]*a.x + A1[4]*b.x + A1[5]*c.x;
        v[2].y = A1[3]*a.y + A1[4]*b.y + A1[5]*c.y;
        v[2].z = A1[3]*a.z + A1[4]*b.z + A1[5]*c.z;
        v[2].w = A1[3]*a.w + A1[4]*b.w + A1[5]*c.w;
        v[3].x = A1[6]*a.x + A1[7]*b.x + A1[8]*c.x;
        v[3].y = A1[6]*a.y + A1[7]*b.y + A1[8]*c.y;
        v[3].z = A1[6]*a.z + A1[7]*b.z + A1[8]*c.z;
        v[3].w = A1[6]*a.w + A1[7]*b.w + A1[8]*c.w;
    }
#pragma unroll
    for (int j = 0; j < 4; j++) m4[(4*tid + j) ^ P] = v[j];
    __syncthreads();
}

__device__ __forceinline__ void rot2dig(float v[16], const float* Alo, const float* Ahi)
{
#pragma unroll
    for (int g = 0; g < 4; g++) {
        float x = v[g*4+1], y = v[g*4+2], z = v[g*4+3];
        v[g*4+1] = Alo[0]*x + Alo[1]*y + Alo[2]*z;
        v[g*4+2] = Alo[3]*x + Alo[4]*y + Alo[5]*z;
        v[g*4+3] = Alo[6]*x + Alo[7]*y + Alo[8]*z;
    }
#pragma unroll
    for (int c = 0; c < 4; c++) {
        float x = v[c+4], y = v[c+8], z = v[c+12];
        v[c+4]  = Ahi[0]*x + Ahi[1]*y + Ahi[2]*z;
        v[c+8]  = Ahi[3]*x + Ahi[4]*y + Ahi[5]*z;
        v[c+12] = Ahi[6]*x + Ahi[7]*y + Ahi[8]*z;
    }
}

__device__ __forceinline__ void rotCD(float* m, const float* A2, const float* A3, int tid)
{
    const int lo = tid & 15, hi = (tid >> 4) << 8;
    float v[16];
#pragma unroll
    for (int e = 0; e < 16; e++) v[e] = m[PHYS(hi | (e << 4) | lo)];
    rot2dig(v, A2, A3);
#pragma unroll
    for (int e = 0; e < 16; e++) m[PHYS(hi | (e << 4) | lo)] = v[e];
    __syncthreads();
}

__device__ __forceinline__ void rotEF(float* m, const float* A4, const float* A5, int tid,
                                      const short* ring, bool dep)
{
    float v[16];
#pragma unroll
    for (int e = 0; e < 16; e++) v[e] = m[PHYS((e << 8) | tid)];
    rot2dig(v, A4, A5);
    if (ring) {
        __syncthreads();
#pragma unroll
        for (int e = 0; e < 16; e++) {
            int s = (e << 8) | tid;
            float val = v[e];
            if (dep) {
                float sc = 1.f;
#pragma unroll
                for (int q = 0; q < 6; q++)
                    if ((s >> (2*q)) & 3) sc *= (q < 5) ? LAM12 : LAM1;
                val *= sc;
            }
            int tg = ring[s];
            m[PHYS(tg & 4095)] = (tg & 4096) ? -val : val;
        }
    } else {
#pragma unroll
        for (int e = 0; e < 16; e++) m[PHYS((e << 8) | tid)] = v[e];
    }
    __syncthreads();
}

// ---------- kernel 1: PTM evolution (blocks 0..5) + 64x64 f32x2 GEMM (6..133) ----------
__global__ void __launch_bounds__(256) k1(const float* __restrict__ x, const float* __restrict__ W1,
                                          const float* __restrict__ sw, const float* __restrict__ tw)
{
    extern __shared__ __align__(16) char su[];
    __shared__ float Mq[6][4];
    __shared__ int sTg;
    const int tid = threadIdx.x;
    const int blk = blockIdx.x;
    const int lane = tid & 31, wrp = tid >> 5;

    if (blk < NPTM) {
        float* m = reinterpret_cast<float*>(su);
        short* rtab = reinterpret_cast<short*>(su + 16384);             // [3][4096]
        float (*mats)[10] = reinterpret_cast<float(*)[10]>(su + 41216); // [30][10]

        {
            const uint4* srcT = reinterpret_cast<const uint4*>(&g_tabs.ring[0][0]);
            uint4* dstT = reinterpret_cast<uint4*>(rtab);
#pragma unroll
            for (int i = 0; i < 6; i++) dstT[tid + i*256] = srcT[tid + i*256];
        }
        if (tid < 30) {
            const float* wsrc = (tid < 18) ? (sw + tid*3) : (tw + (tid - 18)*3);
            float sp, cp, st, ct, sw_, cw_;
            sincosf(wsrc[0], &sp, &cp);
            sincosf(wsrc[1], &st, &ct);
            sincosf(wsrc[2], &sw_, &cw_);
            mats[tid][0] =  cp*ct*cw_ - sp*sw_;
            mats[tid][1] =  cp*ct*sw_ + sp*cw_;
            mats[tid][2] = -cp*st;
            mats[tid][3] = -sp*ct*cw_ - cp*sw_;
            mats[tid][4] = -sp*ct*sw_ + cp*cw_;
            mats[tid][5] =  sp*st;
            mats[tid][6] =  st*cw_;
            mats[tid][7] =  st*sw_;
            mats[tid][8] =  ct;
        }
        const int k = blk;
        if (tid == 0) sTg = g_tabs.ring[1][3 << (2*k)];   // first ring (r=2) analytic
        __syncthreads();

        // per-digit vectors of the product state after the first rot layer
        const int tg0 = sTg;
        if (tid < 24) {
            int q = tid >> 2, j = tid & 3;
            int Pq = (tg0 >> (2*q)) & 3;
            float val;
            if (Pq == 0) val = (j == 0) ? 1.f : 0.f;
            else         val = (j == 0) ? 0.f : mats[24 + q][3*(j-1) + (Pq-1)];
            if (q == 0) val *= (tg0 & 4096) ? -LAM1 : LAM1;
            Mq[q][j] = val;
        }
        __syncthreads();

        // fused pass: materialize product state AND apply ring R1 scatter (bijection: no pre-zero)
        {
            float base = Mq[0][tid & 3] * Mq[1][(tid >> 2) & 3]
                       * Mq[2][(tid >> 4) & 3] * Mq[3][(tid >> 6) & 3];
            float m4v[4], m5v[4];
#pragma unroll
            for (int j = 0; j < 4; j++) { m4v[j] = Mq[4][j]; m5v[j] = Mq[5][j]; }
            const short* r1 = rtab;
#pragma unroll
            for (int e = 0; e < 16; e++) {
                int s = (e << 8) | tid;
                float val = base * m4v[e & 3] * m5v[e >> 2];
                int tg = r1[s];
                m[PHYS(tg & 4095)] = (tg & 4096) ? -val : val;
            }
        }
        __syncthreads();

        rotAB(m, mats[18], mats[19], tid);
        rotCD(m, mats[20], mats[21], tid);
        rotEF(m, mats[22], mats[23], tid, rtab + 2*4096, true);    // + dep + R3
        rotAB(m, mats[12], mats[13], tid);
        rotCD(m, mats[14], mats[15], tid);
        rotEF(m, mats[16], mats[17], tid, rtab + 1*4096, false);   // + R2
        rotAB(m, mats[6],  mats[7],  tid);
        rotCD(m, mats[8],  mats[9],  tid);
        rotEF(m, mats[10], mats[11], tid, rtab + 0*4096, false);   // + R1
        rotAB(m, mats[0],  mats[1],  tid);
        rotCD(m, mats[2],  mats[3],  tid);
        rotEF(m, mats[4],  mats[5],  tid, (const short*)0, false);

        for (int i = tid; i < 768; i += 256)
            g_Tct[i*8 + k] = (i < 729) ? m[PHYS((int)g_tabs.s4of[i])] : 0.f;
    } else {
        const int g    = blk - NPTM;
        const int rowT = g >> 5;            // 0..3 : 64-row tiles
        const int colT = (g >> 3) & 3;      // 0..3 : 64-col tiles
        const int kp   = g & 7;             // 0..7 : 98-K slices
        const int row0 = rowT * 64, col0 = colT * 64;

        float* ws = reinterpret_cast<float*>(su);            // [64][100]
        float* xs = reinterpret_cast<float*>(su + 25600);    // [64][100]

        const float2* W1_2 = reinterpret_cast<const float2*>(W1);
        const float2* x_2  = reinterpret_cast<const float2*>(x);
        const int kof = kp * 49;            // in float2 units

        for (int idx = tid; idx < 64*49; idx += 256) {
            int c = idx / 49, j2 = idx - c*49;
            float2 wv = W1_2[(col0 + c)*392 + kof + j2];
            ws[c*100 + 2*j2]     = wv.x;
            ws[c*100 + 2*j2 + 1] = wv.y;
            float2 xv = x_2[(row0 + c)*392 + kof + j2];
            xs[c*100 + 2*j2]     = xv.x;
            xs[c*100 + 2*j2 + 1] = xv.y;
        }
        if (tid < 128) {
            int c = tid >> 1, o = 98 + (tid & 1);
            ws[c*100 + o] = 0.f;
            xs[c*100 + o] = 0.f;
        }
        __syncthreads();

        const ulonglong2* wA = reinterpret_cast<const ulonglong2*>(ws + lane*100);
        const ulonglong2* wB = reinterpret_cast<const ulonglong2*>(ws + (lane + 32)*100);
        const float* xrow = xs + (wrp * 8) * 100;

        u64 acc[8][2];
#pragma unroll
        for (int r = 0; r < 8; r++) { acc[r][0] = 0ull; acc[r][1] = 0ull; }

#pragma unroll 5
        for (int j = 0; j < 25; j++) {
            ulonglong2 wa = wA[j];
            ulonglong2 wb = wB[j];
#pragma unroll
            for (int r = 0; r < 8; r++) {
                ulonglong2 xv = *reinterpret_cast<const ulonglong2*>(xrow + r*100 + 4*j);
                ffma2(acc[r][0], xv.x, wa.x);
                ffma2(acc[r][0], xv.y, wa.y);
                ffma2(acc[r][1], xv.x, wb.x);
                ffma2(acc[r][1], xv.y, wb.y);
            }
        }
#pragma unroll
        for (int r = 0; r < 8; r++) {
            int row = row0 + wrp*8 + r;
            float2 a0 = *reinterpret_cast<float2*>(&acc[r][0]);
            float2 a1 = *reinterpret_cast<float2*>(&acc[r][1]);
            g_hp[kp*65536 + row*256 + col0 + lane]      = a0.x + a0.y;
            g_hp[kp*65536 + row*256 + col0 + 32 + lane] = a1.x + a1.y;
        }
    }
#if __CUDA_ARCH__ >= 900
    cudaTriggerProgrammaticLaunchCompletion();
#endif
}

// ---------- kernel 2 (PDL secondary): 4-barrier fused tail ----------
__device__ __forceinline__ float pick3(int d, float vx, float vz) {
    return (d == 0) ? 1.f : ((d == 1) ? vx : vz);
}

__global__ void __launch_bounds__(256) k2(const float* __restrict__ b1v,
                                          const float* __restrict__ lng, const float* __restrict__ lnb,
                                          const float* __restrict__ W2, const float* __restrict__ b2,
                                          const float* __restrict__ Wp, const float* __restrict__ bp,
                                          float* __restrict__ out)
{
    __shared__ float4 red[8];
    __shared__ float pw[8][12];
    __shared__ float ploA[27], phiA[27], ploB[27], phiB[27];
    __shared__ float r6A[8][6], r6B[8][6];

    const int tid = threadIdx.x;
    const int lane = tid & 31, w = tid >> 5;
    const int rA = blockIdx.x * 2, rB = rA + 1;

    // ---- k1-independent prefetch (overlaps k1 under PDL) ----
    const float pb1 = b1v[tid], pg = lng[tid], pbb = lnb[tid];
    float w2c[6];
#pragma unroll
    for (int i = 0; i < 6; i++) w2c[i] = W2[i*256 + tid];
    float bwv = 0.f;
    if (w < 2 && lane < 6) bwv = b2[lane];
    float bpv = 0.f, wpr[6];
#pragma unroll
    for (int i = 0; i < 6; i++) wpr[i] = 0.f;
    if (tid < 2) {
        bpv = bp[tid];
#pragma unroll
        for (int i = 0; i < 6; i++) wpr[i] = Wp[tid*6 + i];
    } else if (tid >= 32 && tid < 34) {
        bpv = bp[tid - 32];
#pragma unroll
        for (int i = 0; i < 6; i++) wpr[i] = Wp[(tid - 32)*6 + i];
    }

#if __CUDA_ARCH__ >= 900
    cudaGridDependencySynchronize();
#endif

    // ---- k1-dependent ----
    const float4* Tct4 = reinterpret_cast<const float4*>(g_Tct);
    float4 tA[3], tB[3];
#pragma unroll
    for (int j = 0; j < 3; j++) {
        int ss = tid + j * 256;
        tA[j] = Tct4[ss*2];
        tB[j] = Tct4[ss*2 + 1];
    }

    float hA = pb1, hB = pb1;
#pragma unroll
    for (int p = 0; p < KS; p++) {
        hA += g_hp[p*65536 + rA*HID + tid];
        hB += g_hp[p*65536 + rB*HID + tid];
    }
    hA = fmaxf(hA, 0.f);
    hB = fmaxf(hB, 0.f);

    // phase 1: fused sum+sumsq for both rows; single barrier
    float s0 = hA, q0 = hA*hA, s1 = hB, q1 = hB*hB;
#pragma unroll
    for (int o = 16; o > 0; o >>= 1) {
        s0 += __shfl_down_sync(~0u, s0, o);
        q0 += __shfl_down_sync(~0u, q0, o);
        s1 += __shfl_down_sync(~0u, s1, o);
        q1 += __shfl_down_sync(~0u, q1, o);
    }
    if (lane == 0) red[w] = make_float4(s0, q0, s1, q1);
    __syncthreads();
    float4 Rs = red[0];
#pragma unroll
    for (int i = 1; i < 8; i++) {
        float4 t = red[i];
        Rs.x += t.x; Rs.y += t.y; Rs.z += t.z; Rs.w += t.w;
    }
    float muA = Rs.x * (1.f/256.f), vaA = Rs.y * (1.f/256.f) - muA*muA;
    float muB = Rs.z * (1.f/256.f), vaB = Rs.w * (1.f/256.f) - muB*muB;
    float rsA = rsqrtf(vaA + 1e-5f), rsB = rsqrtf(vaB + 1e-5f);
    float hnAv = (hA - muA) * rsA * pg + pbb;
    float hnBv = (hB - muB) * rsB * pg + pbb;

    // phase 2: per-thread W2 contributions, 12 warp reductions
    float c[12];
#pragma unroll
    for (int i = 0; i < 6; i++) {
        c[i]     = hnAv * w2c[i];
        c[6 + i] = hnBv * w2c[i];
    }
#pragma unroll
    for (int i = 0; i < 12; i++) {
#pragma unroll
        for (int o = 16; o > 0; o >>= 1) c[i] += __shfl_down_sync(~0u, c[i], o);
    }
    if (lane == 0) {
#pragma unroll
        for (int i = 0; i < 12; i++) pw[w][i] = c[i];
    }
    __syncthreads();

    // phase 3: warps 0 (row A) and 1 (row B): p -> z -> Bloch -> half-products
    if (w < 2) {
        float pv = 0.f;
        if (lane < 6) {
#pragma unroll
            for (int ww = 0; ww < 8; ww++) pv += pw[ww][w*6 + lane];
            pv += bwv;
        }
        float z = tanhf(pv);
        float sn, cn;
        sincosf(PI_F * z, &sn, &cn);
        float tx = LAM1 * sn, tz = LAM1 * cn;
        float txs[6], tzs[6];
#pragma unroll
        for (int q2 = 0; q2 < 6; q2++) {
            txs[q2] = __shfl_sync(~0u, tx, q2);
            tzs[q2] = __shfl_sync(~0u, tz, q2);
        }
        if (lane < 27) {
            int d0 = lane % 3, d1 = (lane / 3) % 3, d2 = lane / 9;
            float plo = pick3(d0, txs[0], tzs[0]) * pick3(d1, txs[1], tzs[1]) * pick3(d2, txs[2], tzs[2]);
            float phi = pick3(d0, txs[3], tzs[3]) * pick3(d1, txs[4], tzs[4]) * pick3(d2, txs[5], tzs[5]);
            if (w == 0) { ploA[lane] = plo; phiA[lane] = phi; }
            else        { ploB[lane] = plo; phiB[lane] = phi; }
        }
    }
    __syncthreads();

    // phase 4: 729-term eval for both rows
    float accA[NQ] = {0,0,0,0,0,0}, accB[NQ] = {0,0,0,0,0,0};
#pragma unroll
    for (int j = 0; j < 3; j++) {
        int ss = tid + j * 256;
        int sc = (ss < 729) ? ss : 0;      // padded table rows are zero
        int lo = sc % 27, hi = sc / 27;
        float prA = ploA[lo] * phiA[hi];
        float prB = ploB[lo] * phiB[hi];
        accA[0] = fmaf(prA, tA[j].x, accA[0]); accB[0] = fmaf(prB, tA[j].x, accB[0]);
        accA[1] = fmaf(prA, tA[j].y, accA[1]); accB[1] = fmaf(prB, tA[j].y, accB[1]);
        accA[2] = fmaf(prA, tA[j].z, accA[2]); accB[2] = fmaf(prB, tA[j].z, accB[2]);
        accA[3] = fmaf(prA, tA[j].w, accA[3]); accB[3] = fmaf(prB, tA[j].w, accB[3]);
        accA[4] = fmaf(prA, tB[j].x, accA[4]); accB[4] = fmaf(prB, tB[j].x, accB[4]);
        accA[5] = fmaf(prA, tB[j].y, accA[5]); accB[5] = fmaf(prB, tB[j].y, accB[5]);
    }
#pragma unroll
    for (int k = 0; k < 6; k++) {
#pragma unroll
        for (int o = 16; o > 0; o >>= 1) {
            accA[k] += __shfl_down_sync(~0u, accA[k], o);
            accB[k] += __shfl_down_sync(~0u, accB[k], o);
        }
    }
    if (lane == 0) {
#pragma unroll
        for (int k = 0; k < 6; k++) { r6A[w][k] = accA[k]; r6B[w][k] = accB[k]; }
    }
    __syncthreads();

    // final: 4 threads compute outputs directly
    if (tid < 2) {
        float o = bpv;
#pragma unroll
        for (int k = 0; k < 6; k++) {
            float ev = 0.f;
#pragma unroll
            for (int ww = 0; ww < 8; ww++) ev += r6A[ww][k];
            o = fmaf(ev, wpr[k], o);
        }
        out[rA*2 + tid] = o;
    } else if (tid >= 32 && tid < 34) {
        float o = bpv;
#pragma unroll
        for (int k = 0; k < 6; k++) {
            float ev = 0.f;
#pragma unroll
            for (int ww = 0; ww < 8; ww++) ev += r6B[ww][k];
            o = fmaf(ev, wpr[k], o);
        }
        out[rB*2 + (tid - 32)] = o;
    }
}

extern "C" void kernel_launch(void* const* d_in, const int* in_sizes, int n_in,
                              void* d_out, int out_size)
{
    const float* x        = (const float*)d_in[0];
    const float* W1       = (const float*)d_in[1];
    const float* b1       = (const float*)d_in[2];
    const float* ln_g     = (const float*)d_in[3];
    const float* ln_b     = (const float*)d_in[4];
    const float* W2       = (const float*)d_in[5];
    const float* b2       = (const float*)d_in[6];
    const float* shared_w = (const float*)d_in[7];
    const float* task_w   = (const float*)d_in[8];
    const float* Wp       = (const float*)d_in[9];
    const float* bp       = (const float*)d_in[10];
    float* out = (float*)d_out;

    cudaFuncSetAttribute(k1, cudaFuncAttributeMaxDynamicSharedMemorySize, SMEM_DYN);

    k1<<<NPTM + GEMM_BLOCKS, 256, SMEM_DYN>>>(x, W1, shared_w, task_w);

    cudaLaunchConfig_t cfg = {};
    cfg.gridDim  = dim3(BATCH / 2, 1, 1);
    cfg.blockDim = dim3(256, 1, 1);
    cfg.dynamicSmemBytes = 0;
    cudaLaunchAttribute attrs[1];
    attrs[0].id = cudaLaunchAttributeProgrammaticStreamSerialization;
    attrs[0].val.programmaticStreamSerializationAllowed = 1;
    cfg.attrs = attrs;
    cfg.numAttrs = 1;
    cudaLaunchKernelEx(&cfg, k2, b1, ln_g, ln_b, W2, b2, Wp, bp, out);
}